// round 1
// baseline (speedup 1.0000x reference)
#include <cuda_runtime.h>

#define TABLE_ROWS 1025
#define HIDDEN     128
#define SEQ        512
#define BATCH      2
#define MAXSEQ     512

// Scratch for the projected tables (allocation-free rule: device globals).
__device__ float g_Ass[TABLE_ROWS * HIDDEN];   // pe_ss @ W[:, :128]^T + bias
__device__ float g_Aee[TABLE_ROWS * HIDDEN];   // pe_ee @ W[:, 128:]^T

// ---------------------------------------------------------------------------
// Kernel 1: project the 1025-row tables through the linear layer.
// grid = (ceil(1025/8), 2), block = 128 threads (thread = output h).
// blockIdx.y selects table (0 = ss half of W + bias, 1 = ee half).
// Each block handles 8 table rows; W row segment kept in registers (float4),
// pe rows broadcast from shared memory.
// ---------------------------------------------------------------------------
__global__ void __launch_bounds__(128)
project_tables_kernel(const float* __restrict__ pe_ss,
                      const float* __restrict__ pe_ee,
                      const float* __restrict__ W,
                      const float* __restrict__ bias)
{
    const int sel = blockIdx.y;            // 0 -> ss, 1 -> ee
    const int t0  = blockIdx.x * 8;
    const int h   = threadIdx.x;           // 0..127

    const float* __restrict__ pe = sel ? pe_ee : pe_ss;
    float* __restrict__ outA     = sel ? g_Aee : g_Ass;

    __shared__ float pe_sm[8][HIDDEN];

    #pragma unroll
    for (int r = 0; r < 8; r++) {
        int t = t0 + r;
        pe_sm[r][h] = (t < TABLE_ROWS) ? pe[(size_t)t * HIDDEN + h] : 0.0f;
    }
    __syncthreads();

    float acc[8];
    const float binit = sel ? 0.0f : bias[h];
    #pragma unroll
    for (int r = 0; r < 8; r++) acc[r] = binit;

    // W is [H, 2H] row-major; thread h uses W[h, sel*128 : sel*128+128].
    const float4* __restrict__ W4 =
        reinterpret_cast<const float4*>(W + (size_t)h * (2 * HIDDEN) + sel * HIDDEN);

    #pragma unroll 8
    for (int kg = 0; kg < HIDDEN / 4; kg++) {
        const float4 w = W4[kg];
        #pragma unroll
        for (int r = 0; r < 8; r++) {
            const float4 p = reinterpret_cast<const float4*>(pe_sm[r])[kg]; // broadcast
            acc[r] += w.x * p.x + w.y * p.y + w.z * p.z + w.w * p.w;
        }
    }

    #pragma unroll
    for (int r = 0; r < 8; r++) {
        int t = t0 + r;
        if (t < TABLE_ROWS) outA[(size_t)t * HIDDEN + h] = acc[r];
    }
}

// ---------------------------------------------------------------------------
// Kernel 2: out[b,i,j,:] = relu(A_ss[ps[i]-ps[j]+512] + A_ee[pe[i]-pe[j]+512])
// grid = B*SEQ blocks (one per (b,i)), block = 256 threads = 8 warps.
// Position rows cached in SMEM; one warp per j-row; float4 gathers + stores.
// ---------------------------------------------------------------------------
__global__ void __launch_bounds__(256)
fuse_gather_kernel(const int* __restrict__ pos_s,
                   const int* __restrict__ pos_e,
                   float* __restrict__ out)
{
    const int bi = blockIdx.x;          // b*SEQ + i
    const int b  = bi >> 9;
    const int i  = bi & (SEQ - 1);

    __shared__ int ps_sm[SEQ];
    __shared__ int pe_sm[SEQ];
    for (int j = threadIdx.x; j < SEQ; j += blockDim.x) {
        ps_sm[j] = pos_s[b * SEQ + j];
        pe_sm[j] = pos_e[b * SEQ + j];
    }
    __syncthreads();

    const int psi = ps_sm[i];
    const int pei = pe_sm[i];

    const int warp = threadIdx.x >> 5;
    const int lane = threadIdx.x & 31;

    const float4* __restrict__ Ass4 = reinterpret_cast<const float4*>(g_Ass);
    const float4* __restrict__ Aee4 = reinterpret_cast<const float4*>(g_Aee);
    float4* __restrict__ out4 =
        reinterpret_cast<float4*>(out + (size_t)bi * SEQ * HIDDEN);

    for (int j = warp; j < SEQ; j += 8) {
        const int iss = psi - ps_sm[j] + MAXSEQ;   // in [1, 1023]
        const int iee = pei - pe_sm[j] + MAXSEQ;

        const float4 a = Ass4[iss * (HIDDEN / 4) + lane];
        const float4 e = Aee4[iee * (HIDDEN / 4) + lane];

        float4 r;
        r.x = fmaxf(a.x + e.x, 0.0f);
        r.y = fmaxf(a.y + e.y, 0.0f);
        r.z = fmaxf(a.z + e.z, 0.0f);
        r.w = fmaxf(a.w + e.w, 0.0f);

        out4[j * (HIDDEN / 4) + lane] = r;
    }
}

// ---------------------------------------------------------------------------
// Inputs (metadata order): 0 pos_s [B,S] i32, 1 pos_e [B,S] i32,
// 2 pe_ss [1025,128] f32, 3 pe_se (unused), 4 pe_es (unused),
// 5 pe_ee [1025,128] f32, 6 W [128,256] f32, 7 b [128] f32.
// Output: [B,S,S,H] f32.
// ---------------------------------------------------------------------------
extern "C" void kernel_launch(void* const* d_in, const int* in_sizes, int n_in,
                              void* d_out, int out_size)
{
    const int*   pos_s = (const int*)d_in[0];
    const int*   pos_e = (const int*)d_in[1];
    const float* pe_ss = (const float*)d_in[2];
    const float* pe_ee = (const float*)d_in[5];
    const float* W     = (const float*)d_in[6];
    const float* bias  = (const float*)d_in[7];
    float*       out   = (float*)d_out;

    dim3 grid1((TABLE_ROWS + 7) / 8, 2);
    project_tables_kernel<<<grid1, 128>>>(pe_ss, pe_ee, W, bias);

    fuse_gather_kernel<<<BATCH * SEQ, 256>>>(pos_s, pos_e, out);
}